// round 14
// baseline (speedup 1.0000x reference)
#include <cuda_runtime.h>
#include <cuda_bf16.h>
#include <math_constants.h>
#include <mma.h>

using namespace nvcuda;

// Problem constants
#define B_    128
#define T_    1024
#define D_    512
#define V_    128
#define L_    128
#define S_    257           // 2L+1
#define BLANK_ 127          // V-1
#define EPS_  1e-7f
#define NEG_  (-1e30f)
#define LN2_  0.6931471805599453f

// GEMM tiling (R6/R7 configuration — fastest measured, twice)
#define BM 128
#define BN 128
#define BK 32
#define APAD 8
#define BPAD 8
#define CPAD 4

// Scratch: log2(softmax prob + eps) [B,T,V] fp32 (64 MB), per-example losses
static __device__ float g_lp[B_ * T_ * V_];
static __device__ float g_loss[B_];

__device__ __forceinline__ float fexp2(float x) {
    float y; asm("ex2.approx.ftz.f32 %0, %1;" : "=f"(y) : "f"(x)); return y;
}

__device__ __forceinline__ void st4bf16(__nv_bfloat16* dst, float4 v) {
    __nv_bfloat162 p0; p0.x = __float2bfloat16(v.x); p0.y = __float2bfloat16(v.y);
    __nv_bfloat162 p1; p1.x = __float2bfloat16(v.z); p1.y = __float2bfloat16(v.w);
    *(__nv_bfloat162*)(dst)     = p0;
    *(__nv_bfloat162*)(dst + 2) = p1;
}

// ---------------------------------------------------------------------------
// Kernel 1: bf16 WMMA GEMM (logits = X @ W + b) + softmax -> g_lp = log2(p+eps)
// R6/R7 code verbatim (175.6 us measured twice). Block 128x128, BK=32,
// 8 warps (4M x 2N), warp tile 32x64, fp32 accumulate.
// ---------------------------------------------------------------------------
__global__ __launch_bounds__(256) void gemm_softmax_kernel(
    const float* __restrict__ X, const float* __restrict__ W,
    const float* __restrict__ bias)
{
    __shared__ __nv_bfloat16 As[BM][BK + APAD];   // 128 x 40
    __shared__ __nv_bfloat16 Bs[BK][BN + BPAD];   //  32 x 136
    __shared__ float         Cs[32][BN + CPAD];   //  32 x 132

    const int tid = threadIdx.x;
    const int wid = tid >> 5;
    const int warp_m = wid & 3;       // 0..3
    const int warp_n = wid >> 2;      // 0..1
    const int rowBase = blockIdx.x * BM;

    wmma::fragment<wmma::accumulator, 16, 16, 16, float> cfrag[2][4];
#pragma unroll
    for (int i = 0; i < 2; ++i)
#pragma unroll
        for (int j = 0; j < 4; ++j) wmma::fill_fragment(cfrag[i][j], 0.f);

    const int ar = tid >> 1;
    const int ac = (tid & 1) * 16;
    const int br = tid >> 3;
    const int bc = (tid & 7) * 16;
    const float* Ap = X + (size_t)(rowBase + ar) * D_ + ac;
    const float* Bp = W + (size_t)br * V_ + bc;

    for (int k0 = 0; k0 < D_; k0 += BK) {
        float4 a0 = *(const float4*)(Ap + k0);
        float4 a1 = *(const float4*)(Ap + k0 + 4);
        float4 a2 = *(const float4*)(Ap + k0 + 8);
        float4 a3 = *(const float4*)(Ap + k0 + 12);
        float4 b0 = *(const float4*)(Bp + (size_t)k0 * V_);
        float4 b1 = *(const float4*)(Bp + (size_t)k0 * V_ + 4);
        float4 b2 = *(const float4*)(Bp + (size_t)k0 * V_ + 8);
        float4 b3 = *(const float4*)(Bp + (size_t)k0 * V_ + 12);
        st4bf16(&As[ar][ac + 0], a0);  st4bf16(&As[ar][ac + 4], a1);
        st4bf16(&As[ar][ac + 8], a2);  st4bf16(&As[ar][ac + 12], a3);
        st4bf16(&Bs[br][bc + 0], b0);  st4bf16(&Bs[br][bc + 4], b1);
        st4bf16(&Bs[br][bc + 8], b2);  st4bf16(&Bs[br][bc + 12], b3);
        __syncthreads();

#pragma unroll
        for (int kk = 0; kk < BK; kk += 16) {
            wmma::fragment<wmma::matrix_a, 16, 16, 16, __nv_bfloat16, wmma::row_major> af[2];
            wmma::fragment<wmma::matrix_b, 16, 16, 16, __nv_bfloat16, wmma::row_major> bf[4];
#pragma unroll
            for (int i = 0; i < 2; ++i)
                wmma::load_matrix_sync(af[i], &As[warp_m * 32 + i * 16][kk], BK + APAD);
#pragma unroll
            for (int j = 0; j < 4; ++j)
                wmma::load_matrix_sync(bf[j], &Bs[kk][warp_n * 64 + j * 16], BN + BPAD);
#pragma unroll
            for (int i = 0; i < 2; ++i)
#pragma unroll
                for (int j = 0; j < 4; ++j)
                    wmma::mma_sync(cfrag[i][j], af[i], bf[j], cfrag[i][j]);
        }
        __syncthreads();
    }

    // Epilogue: 4 passes of 32 rows. Softmax per row, write log2(p + eps).
    const int tx = tid & 15;
    const int ty = tid >> 4;
    float bb[8];
#pragma unroll
    for (int j = 0; j < 8; ++j) bb[j] = bias[tx * 8 + j];

    for (int wm = 0; wm < 4; ++wm) {
        if (warp_m == wm) {
#pragma unroll
            for (int i = 0; i < 2; ++i)
#pragma unroll
                for (int j = 0; j < 4; ++j)
                    wmma::store_matrix_sync(&Cs[i * 16][warp_n * 64 + j * 16],
                                            cfrag[i][j], BN + CPAD, wmma::mem_row_major);
        }
        __syncthreads();
#pragma unroll
        for (int r = 0; r < 2; ++r) {
            const int row = ty * 2 + r;
            float l[8];
            float rmax = -CUDART_INF_F;
#pragma unroll
            for (int j = 0; j < 8; ++j) {
                l[j] = Cs[row][tx * 8 + j] + bb[j];
                rmax = fmaxf(rmax, l[j]);
            }
#pragma unroll
            for (int m = 1; m <= 8; m <<= 1)
                rmax = fmaxf(rmax, __shfl_xor_sync(0xFFFFFFFFu, rmax, m));
            float s = 0.f;
#pragma unroll
            for (int j = 0; j < 8; ++j) { l[j] = __expf(l[j] - rmax); s += l[j]; }
#pragma unroll
            for (int m = 1; m <= 8; m <<= 1)
                s += __shfl_xor_sync(0xFFFFFFFFu, s, m);
            float invs = 1.f / s;
            float* orow = g_lp + (size_t)(rowBase + wm * 32 + row) * V_ + tx * 8;
            float4 o0, o1;
            o0.x = __log2f(l[0] * invs + EPS_); o0.y = __log2f(l[1] * invs + EPS_);
            o0.z = __log2f(l[2] * invs + EPS_); o0.w = __log2f(l[3] * invs + EPS_);
            o1.x = __log2f(l[4] * invs + EPS_); o1.y = __log2f(l[5] * invs + EPS_);
            o1.z = __log2f(l[6] * invs + EPS_); o1.w = __log2f(l[7] * invs + EPS_);
            *(float4*)orow = o0;
            *(float4*)(orow + 4) = o1;
        }
        __syncthreads();
    }
}

// ---------------------------------------------------------------------------
// Kernel 2: CTC forward DP, log2 domain — TWO steps per barrier via warp halo.
// 9 warps (288 thr); lane owns state s = warp*30 + lane - 2 (2-state overlap
// between adjacent warps). Per superstep: lanes 0,1 refresh from the smem
// snapshot (GUARDED: s may be negative in warp 0 -> NEG, not OOB);
// step A uses shfl_up + smem boundaries (all 32 lanes valid);
// step B uses shfl_up only (lanes >=2 valid = the net 30 states/warp);
// publish lanes 2..31 (exactly covers 0..256), ONE __syncthreads.
// Emissions: 16-deep statically-indexed FIFO over an unroll-8-superstep loop.
// ---------------------------------------------------------------------------
__global__ __launch_bounds__(288) void ctc_kernel(
    const int* __restrict__ targets, const int* __restrict__ tlen)
{
    __shared__ float buf[2][S_];
    __shared__ int   exts[S_];

    const int b    = blockIdx.x;
    const int tid  = threadIdx.x;
    const int warp = tid >> 5;        // 0..8
    const int lane = tid & 31;
    const int s    = warp * 30 + lane - 2;      // -2 .. 268
    const bool sval = (s >= 0 && s < S_);
    const bool pub  = (lane >= 2) && (s < S_);  // publishers cover 0..256 exactly
    const float* LP = g_lp + (size_t)b * T_ * V_;

    if (tid < S_) exts[tid] = (tid & 1) ? targets[b * L_ + (tid >> 1)] : BLANK_;
    __syncthreads();

    int  myext  = BLANK_;
    bool allow2 = false;
    if (sval) {
        myext  = exts[s];
        allow2 = (s & 1) && (s >= 2) && (myext != exts[s - 2]);
    }

    // t = 0 init (every lane computes its own state's value locally)
    float a = (sval && s < 2) ? LP[myext] : NEG_;
    if (pub) buf[0][s] = a;

    // emission FIFO: e[j] = step 1+j  (j = 0..15)
    float e[16];
#pragma unroll
    for (int j = 0; j < 16; ++j) e[j] = LP[(size_t)(1 + j) * V_ + myext];
    __syncthreads();

    int p = 0;   // buf[p] = latest published alpha row

#define CTC_STEP_A(EA)                                                       \
    {   float bl1 = NEG_, bl2 = NEG_;                                        \
        if (lane == 0) {                                                     \
            a   = (s >= 0) ? buf[p][s]     : NEG_;                           \
            bl1 = (s >= 1) ? buf[p][s - 1] : NEG_;                           \
            bl2 = (s >= 2) ? buf[p][s - 2] : NEG_;                           \
        } else if (lane == 1) {                                              \
            a   = (s >= 0) ? buf[p][s]     : NEG_;                           \
            bl2 = (s >= 2) ? buf[p][s - 2] : NEG_;                           \
        }                                                                    \
        float a1 = __shfl_up_sync(0xFFFFFFFFu, a, 1);                        \
        float a2 = __shfl_up_sync(0xFFFFFFFFu, a, 2);                        \
        if (lane == 0) { a1 = bl1; a2 = bl2; }                               \
        else if (lane == 1) { a2 = bl2; }                                    \
        float a2v = allow2 ? a2 : NEG_;                                      \
        float m = fmaxf(fmaxf(a, a1), a2v);                                  \
        a = m + __log2f(fexp2(a - m) + fexp2(a1 - m) + fexp2(a2v - m)) + (EA); \
        if (s < 0) a = NEG_;                                                 \
    }
#define CTC_STEP_B(EB)                                                       \
    {   float a1 = __shfl_up_sync(0xFFFFFFFFu, a, 1);                        \
        float a2 = __shfl_up_sync(0xFFFFFFFFu, a, 2);                        \
        float a2v = allow2 ? a2 : NEG_;                                      \
        float m = fmaxf(fmaxf(a, a1), a2v);                                  \
        a = m + __log2f(fexp2(a - m) + fexp2(a1 - m) + fexp2(a2v - m)) + (EB); \
        if (s < 0) a = NEG_;                                                 \
    }

    // Main: 63 iterations x 8 supersteps = 504 supersteps = steps t = 1..1008
    for (int i = 0; i < 63; ++i) {
        const int tb = 16 * i;
#pragma unroll
        for (int j = 0; j < 8; ++j) {
            const int t = tb + 2 * j + 1;          // step A time
            float eA = e[2 * j], eB = e[2 * j + 1];
            // reload FIFO slots for t+16 / t+17 (consumed 8 supersteps later)
            if (t + 16 < T_) e[2 * j]     = LP[(size_t)(t + 16) * V_ + myext];
            if (t + 17 < T_) e[2 * j + 1] = LP[(size_t)(t + 17) * V_ + myext];
            CTC_STEP_A(eA);
            CTC_STEP_B(eB);
            if (pub) buf[p ^ 1][s] = a;
            __syncthreads();
            p ^= 1;
        }
    }
    // Tail supersteps: t = (1009,1010) .. (1021,1022), e[0..13]
#pragma unroll
    for (int k = 0; k < 7; ++k) {
        CTC_STEP_A(e[2 * k]);
        CTC_STEP_B(e[2 * k + 1]);
        if (pub) buf[p ^ 1][s] = a;
        __syncthreads();
        p ^= 1;
    }
    // Final single step t = 1023 (e[14]); step A alone is valid on all lanes.
    CTC_STEP_A(e[14]);
    if (pub) buf[p ^ 1][s] = a;
    __syncthreads();
    p ^= 1;
#undef CTC_STEP_A
#undef CTC_STEP_B

    if (tid == 0) {
        const int last = 2 * tlen[b];              // 32..256
        float aN  = buf[p][last];
        float aN1 = buf[p][last - 1];
        float m   = fmaxf(aN, aN1);
        g_loss[b] = -LN2_ * (m + __log2f(fexp2(aN - m) + fexp2(aN1 - m)));
    }
}

// ---------------------------------------------------------------------------
// Kernel 3: deterministic fixed-order sum of the 128 losses.
// ---------------------------------------------------------------------------
__global__ __launch_bounds__(128) void sum_kernel(float* __restrict__ out)
{
    __shared__ float s[128];
    const int t = threadIdx.x;
    s[t] = g_loss[t];
    __syncthreads();
    for (int o = 64; o > 0; o >>= 1) {
        if (t < o) s[t] += s[t + o];
        __syncthreads();
    }
    if (t == 0) out[0] = s[0];
}

extern "C" void kernel_launch(void* const* d_in, const int* in_sizes, int n_in,
                              void* d_out, int out_size)
{
    (void)in_sizes; (void)n_in; (void)out_size;
    const float* x       = (const float*)d_in[0];
    const float* W       = (const float*)d_in[1];
    const float* bias    = (const float*)d_in[2];
    const int*   targets = (const int*)d_in[3];
    const int*   tlength = (const int*)d_in[4];

    gemm_softmax_kernel<<<(B_ * T_) / BM, 256>>>(x, W, bias);
    ctc_kernel<<<B_, 288>>>(targets, tlength);
    sum_kernel<<<1, 128>>>((float*)d_out);
}

// round 15
// speedup vs baseline: 1.2951x; 1.2951x over previous
#include <cuda_runtime.h>
#include <cuda_bf16.h>
#include <math_constants.h>
#include <mma.h>

using namespace nvcuda;

// Problem constants
#define B_    128
#define T_    1024
#define D_    512
#define V_    128
#define L_    128
#define S_    257           // 2L+1
#define BLANK_ 127          // V-1
#define EPS_  1e-7f
#define NEG_  (-1e30f)
#define LN2_  0.6931471805599453f
#define TMID_ 512           // meet point: forward owns t<=511, backward t>=512

// GEMM tiling (R6/R7 configuration — fastest measured, 3x)
#define BM 128
#define BN 128
#define BK 32
#define APAD 8
#define BPAD 8
#define CPAD 4

// Scratch
static __device__ float g_lp[B_ * T_ * V_];    // log2(softmax+eps), 64 MB
static __device__ float g_amid[B_ * S_];       // forward alpha at t=511
static __device__ float g_bmid[B_ * S_];       // backward gamma at t=511
static __device__ float g_loss[B_];

__device__ __forceinline__ float fexp2(float x) {
    float y; asm("ex2.approx.ftz.f32 %0, %1;" : "=f"(y) : "f"(x)); return y;
}

__device__ __forceinline__ void st4bf16(__nv_bfloat16* dst, float4 v) {
    __nv_bfloat162 p0; p0.x = __float2bfloat16(v.x); p0.y = __float2bfloat16(v.y);
    __nv_bfloat162 p1; p1.x = __float2bfloat16(v.z); p1.y = __float2bfloat16(v.w);
    *(__nv_bfloat162*)(dst)     = p0;
    *(__nv_bfloat162*)(dst + 2) = p1;
}

// ---------------------------------------------------------------------------
// Kernel 1: bf16 WMMA GEMM (logits = X @ W + b) + softmax -> g_lp = log2(p+eps)
// R6/R7 code verbatim (175.5 us, reproduced 3x). Block 128x128, BK=32,
// 8 warps (4M x 2N), warp tile 32x64, fp32 accumulate.
// ---------------------------------------------------------------------------
__global__ __launch_bounds__(256) void gemm_softmax_kernel(
    const float* __restrict__ X, const float* __restrict__ W,
    const float* __restrict__ bias)
{
    __shared__ __nv_bfloat16 As[BM][BK + APAD];   // 128 x 40
    __shared__ __nv_bfloat16 Bs[BK][BN + BPAD];   //  32 x 136
    __shared__ float         Cs[32][BN + CPAD];   //  32 x 132

    const int tid = threadIdx.x;
    const int wid = tid >> 5;
    const int warp_m = wid & 3;       // 0..3
    const int warp_n = wid >> 2;      // 0..1
    const int rowBase = blockIdx.x * BM;

    wmma::fragment<wmma::accumulator, 16, 16, 16, float> cfrag[2][4];
#pragma unroll
    for (int i = 0; i < 2; ++i)
#pragma unroll
        for (int j = 0; j < 4; ++j) wmma::fill_fragment(cfrag[i][j], 0.f);

    const int ar = tid >> 1;
    const int ac = (tid & 1) * 16;
    const int br = tid >> 3;
    const int bc = (tid & 7) * 16;
    const float* Ap = X + (size_t)(rowBase + ar) * D_ + ac;
    const float* Bp = W + (size_t)br * V_ + bc;

    for (int k0 = 0; k0 < D_; k0 += BK) {
        float4 a0 = *(const float4*)(Ap + k0);
        float4 a1 = *(const float4*)(Ap + k0 + 4);
        float4 a2 = *(const float4*)(Ap + k0 + 8);
        float4 a3 = *(const float4*)(Ap + k0 + 12);
        float4 b0 = *(const float4*)(Bp + (size_t)k0 * V_);
        float4 b1 = *(const float4*)(Bp + (size_t)k0 * V_ + 4);
        float4 b2 = *(const float4*)(Bp + (size_t)k0 * V_ + 8);
        float4 b3 = *(const float4*)(Bp + (size_t)k0 * V_ + 12);
        st4bf16(&As[ar][ac + 0], a0);  st4bf16(&As[ar][ac + 4], a1);
        st4bf16(&As[ar][ac + 8], a2);  st4bf16(&As[ar][ac + 12], a3);
        st4bf16(&Bs[br][bc + 0], b0);  st4bf16(&Bs[br][bc + 4], b1);
        st4bf16(&Bs[br][bc + 8], b2);  st4bf16(&Bs[br][bc + 12], b3);
        __syncthreads();

#pragma unroll
        for (int kk = 0; kk < BK; kk += 16) {
            wmma::fragment<wmma::matrix_a, 16, 16, 16, __nv_bfloat16, wmma::row_major> af[2];
            wmma::fragment<wmma::matrix_b, 16, 16, 16, __nv_bfloat16, wmma::row_major> bf[4];
#pragma unroll
            for (int i = 0; i < 2; ++i)
                wmma::load_matrix_sync(af[i], &As[warp_m * 32 + i * 16][kk], BK + APAD);
#pragma unroll
            for (int j = 0; j < 4; ++j)
                wmma::load_matrix_sync(bf[j], &Bs[kk][warp_n * 64 + j * 16], BN + BPAD);
#pragma unroll
            for (int i = 0; i < 2; ++i)
#pragma unroll
                for (int j = 0; j < 4; ++j)
                    wmma::mma_sync(cfrag[i][j], af[i], bf[j], cfrag[i][j]);
        }
        __syncthreads();
    }

    // Epilogue: 4 passes of 32 rows. Softmax per row, write log2(p + eps).
    const int tx = tid & 15;
    const int ty = tid >> 4;
    float bb[8];
#pragma unroll
    for (int j = 0; j < 8; ++j) bb[j] = bias[tx * 8 + j];

    for (int wm = 0; wm < 4; ++wm) {
        if (warp_m == wm) {
#pragma unroll
            for (int i = 0; i < 2; ++i)
#pragma unroll
                for (int j = 0; j < 4; ++j)
                    wmma::store_matrix_sync(&Cs[i * 16][warp_n * 64 + j * 16],
                                            cfrag[i][j], BN + CPAD, wmma::mem_row_major);
        }
        __syncthreads();
#pragma unroll
        for (int r = 0; r < 2; ++r) {
            const int row = ty * 2 + r;
            float l[8];
            float rmax = -CUDART_INF_F;
#pragma unroll
            for (int j = 0; j < 8; ++j) {
                l[j] = Cs[row][tx * 8 + j] + bb[j];
                rmax = fmaxf(rmax, l[j]);
            }
#pragma unroll
            for (int m = 1; m <= 8; m <<= 1)
                rmax = fmaxf(rmax, __shfl_xor_sync(0xFFFFFFFFu, rmax, m));
            float s = 0.f;
#pragma unroll
            for (int j = 0; j < 8; ++j) { l[j] = __expf(l[j] - rmax); s += l[j]; }
#pragma unroll
            for (int m = 1; m <= 8; m <<= 1)
                s += __shfl_xor_sync(0xFFFFFFFFu, s, m);
            float invs = 1.f / s;
            float* orow = g_lp + (size_t)(rowBase + wm * 32 + row) * V_ + tx * 8;
            float4 o0, o1;
            o0.x = __log2f(l[0] * invs + EPS_); o0.y = __log2f(l[1] * invs + EPS_);
            o0.z = __log2f(l[2] * invs + EPS_); o0.w = __log2f(l[3] * invs + EPS_);
            o1.x = __log2f(l[4] * invs + EPS_); o1.y = __log2f(l[5] * invs + EPS_);
            o1.z = __log2f(l[6] * invs + EPS_); o1.w = __log2f(l[7] * invs + EPS_);
            *(float4*)orow = o0;
            *(float4*)(orow + 4) = o1;
        }
        __syncthreads();
    }
}

// ---------------------------------------------------------------------------
// Kernel 2: CTC meet-in-the-middle. 256 blocks x 288 threads.
// Blocks 0..127: FORWARD alpha for example b = blockIdx.x, steps t=1..511
//   (R7 step verbatim: smem double buffer, 8-deep static emission FIFO).
//   Writes alpha_511 -> g_amid.
// Blocks 128..255: BACKWARD betaE for b = blockIdx.x-128, seeded at t=1023
//   from {2len, 2len-1}, steps t=1022..512, then the no-emission gamma
//   half-step. Writes gamma_511 -> g_bmid.
// Sequential depth per block: 511 steps (vs 1023) — the halves run
// concurrently across the grid.
// ---------------------------------------------------------------------------
__global__ __launch_bounds__(288) void ctc_fb_kernel(
    const int* __restrict__ targets, const int* __restrict__ tlen)
{
    __shared__ float buf[2][S_];
    __shared__ int   exts[S_];

    const int bid = blockIdx.x;
    const bool fw = (bid < B_);
    const int b   = fw ? bid : bid - B_;
    const int tid = threadIdx.x;
    const bool act = (tid < S_);
    const float* LP = g_lp + (size_t)b * T_ * V_;

    if (act) exts[tid] = (tid & 1) ? targets[b * L_ + (tid >> 1)] : BLANK_;
    __syncthreads();

    int myext = BLANK_;
    if (act) myext = exts[tid];

    if (fw) {
        // ---------------- FORWARD: t = 1..511 ----------------
        const bool allow2 = act && (tid & 1) && (tid >= 2) && (myext != exts[tid - 2]);
        if (act) buf[0][tid] = (tid < 2) ? LP[myext] : NEG_;
        float e[8];
#pragma unroll
        for (int j = 0; j < 8; ++j) e[j] = LP[(size_t)(1 + j) * V_ + myext];
        __syncthreads();

        // 63 chunks of 8: t = 1..504; tail 7: t = 505..511
        for (int t0 = 1; t0 <= TMID_ - 15; t0 += 8) {
#pragma unroll
            for (int j = 0; j < 8; ++j) {
                const int cur  = (1 + j) & 1;     // t0 odd -> parity (1+j)&1
                const int prev = cur ^ 1;
                if (act) {
                    float a  = buf[prev][tid];
                    float a1 = (tid >= 1) ? buf[prev][tid - 1] : NEG_;
                    float a2 = allow2 ? buf[prev][tid - 2] : NEG_;
                    float m  = fmaxf(fmaxf(a, a1), a2);
                    float s  = fexp2(a - m) + fexp2(a1 - m) + fexp2(a2 - m);
                    buf[cur][tid] = m + __log2f(s) + e[j];
                }
                const int tn = t0 + 8 + j;
                if (tn < TMID_) e[j] = LP[(size_t)tn * V_ + myext];
                __syncthreads();
            }
        }
#pragma unroll
        for (int j = 0; j < 7; ++j) {             // t = 505..511
            const int cur  = (505 + j) & 1;
            const int prev = cur ^ 1;
            if (act) {
                float a  = buf[prev][tid];
                float a1 = (tid >= 1) ? buf[prev][tid - 1] : NEG_;
                float a2 = allow2 ? buf[prev][tid - 2] : NEG_;
                float m  = fmaxf(fmaxf(a, a1), a2);
                float s  = fexp2(a - m) + fexp2(a1 - m) + fexp2(a2 - m);
                buf[cur][tid] = m + __log2f(s) + e[j];
            }
            __syncthreads();
        }
        // t = 511 odd -> buf[1]
        if (act) g_amid[b * S_ + tid] = buf[1][tid];
    } else {
        // ---------------- BACKWARD: t = 1022..512, then gamma ----------------
        // succ(s) = {s, s+1, s+2}; s->s+2 allowed iff s odd and ext[s+2]!=ext[s].
        bool allow2b = false;
        if (act && (tid & 1) && (tid + 2 < S_)) allow2b = (exts[tid + 2] != myext);
        const int last = 2 * tlen[b];             // 32..256
        // init t=1023 (odd -> buf[1]): betaE = e_1023 on end states
        if (act) buf[1][tid] = (tid == last || tid == last - 1)
                                   ? LP[(size_t)1023 * V_ + myext] : NEG_;
        float e[8];
#pragma unroll
        for (int j = 0; j < 8; ++j) e[j] = LP[(size_t)(1022 - j) * V_ + myext];
        __syncthreads();

        // 63 chunks of 8: t = 1022..519; tail 7: t = 518..512
        for (int t0 = 1022; t0 >= 519 + 7; t0 -= 8) {
#pragma unroll
            for (int j = 0; j < 8; ++j) {
                const int t    = t0 - j;
                const int cur  = t & 1;           // row t+1 lives in cur^1
                const int prev = cur ^ 1;
                if (act) {
                    float v0 = buf[prev][tid];
                    float v1 = (tid + 1 < S_) ? buf[prev][tid + 1] : NEG_;
                    float v2 = allow2b ? buf[prev][tid + 2] : NEG_;
                    float m  = fmaxf(fmaxf(v0, v1), v2);
                    float s  = fexp2(v0 - m) + fexp2(v1 - m) + fexp2(v2 - m);
                    buf[cur][tid] = m + __log2f(s) + e[j];
                }
                const int tn = t - 8;
                if (tn >= TMID_) e[j] = LP[(size_t)tn * V_ + myext];
                __syncthreads();
            }
        }
#pragma unroll
        for (int j = 0; j < 7; ++j) {             // t = 518..512
            const int t    = 518 - j;
            const int cur  = t & 1;
            const int prev = cur ^ 1;
            if (act) {
                float v0 = buf[prev][tid];
                float v1 = (tid + 1 < S_) ? buf[prev][tid + 1] : NEG_;
                float v2 = allow2b ? buf[prev][tid + 2] : NEG_;
                float m  = fmaxf(fmaxf(v0, v1), v2);
                float s  = fexp2(v0 - m) + fexp2(v1 - m) + fexp2(v2 - m);
                buf[cur][tid] = m + __log2f(s) + e[j];
            }
            __syncthreads();
        }
        // betaE_512 in buf[0]. Gamma half-step (no emission) -> g_bmid.
        if (act) {
            float v0 = buf[0][tid];
            float v1 = (tid + 1 < S_) ? buf[0][tid + 1] : NEG_;
            float v2 = allow2b ? buf[0][tid + 2] : NEG_;
            float m  = fmaxf(fmaxf(v0, v1), v2);
            float s  = fexp2(v0 - m) + fexp2(v1 - m) + fexp2(v2 - m);
            g_bmid[b * S_ + tid] = m + __log2f(s);
        }
    }
}

// ---------------------------------------------------------------------------
// Kernel 3: combine — per-example logsumexp over 257 states (deterministic
// fixed-order reduction), loss[b] = -ln2 * log2 sum_s 2^(amid+gmid).
// ---------------------------------------------------------------------------
__global__ __launch_bounds__(288) void combine_kernel(void)
{
    __shared__ float wred[9];
    const int b    = blockIdx.x;
    const int tid  = threadIdx.x;
    const int lane = tid & 31;
    const int warp = tid >> 5;
    const bool act = (tid < S_);

    float v = act ? (g_amid[b * S_ + tid] + g_bmid[b * S_ + tid]) : NEG_;

    // block max
    float m = v;
#pragma unroll
    for (int o = 16; o > 0; o >>= 1)
        m = fmaxf(m, __shfl_xor_sync(0xFFFFFFFFu, m, o));
    if (lane == 0) wred[warp] = m;
    __syncthreads();
    float M = wred[0];
#pragma unroll
    for (int w = 1; w < 9; ++w) M = fmaxf(M, wred[w]);
    __syncthreads();

    // block sum of 2^(v-M)
    float s = act ? fexp2(v - M) : 0.f;
#pragma unroll
    for (int o = 16; o > 0; o >>= 1)
        s += __shfl_xor_sync(0xFFFFFFFFu, s, o);
    if (lane == 0) wred[warp] = s;
    __syncthreads();
    if (tid == 0) {
        float tot = wred[0];
#pragma unroll
        for (int w = 1; w < 9; ++w) tot += wred[w];
        g_loss[b] = -LN2_ * (M + __log2f(tot));
    }
}

// ---------------------------------------------------------------------------
// Kernel 4: deterministic fixed-order sum of the 128 losses.
// ---------------------------------------------------------------------------
__global__ __launch_bounds__(128) void sum_kernel(float* __restrict__ out)
{
    __shared__ float s[128];
    const int t = threadIdx.x;
    s[t] = g_loss[t];
    __syncthreads();
    for (int o = 64; o > 0; o >>= 1) {
        if (t < o) s[t] += s[t + o];
        __syncthreads();
    }
    if (t == 0) out[0] = s[0];
}

extern "C" void kernel_launch(void* const* d_in, const int* in_sizes, int n_in,
                              void* d_out, int out_size)
{
    (void)in_sizes; (void)n_in; (void)out_size;
    const float* x       = (const float*)d_in[0];
    const float* W       = (const float*)d_in[1];
    const float* bias    = (const float*)d_in[2];
    const int*   targets = (const int*)d_in[3];
    const int*   tlength = (const int*)d_in[4];

    gemm_softmax_kernel<<<(B_ * T_) / BM, 256>>>(x, W, bias);
    ctc_fb_kernel<<<2 * B_, 288>>>(targets, tlength);
    combine_kernel<<<B_, 288>>>();
    sum_kernel<<<1, 128>>>((float*)d_out);
}

// round 16
// speedup vs baseline: 1.3020x; 1.0053x over previous
#include <cuda_runtime.h>
#include <cuda_bf16.h>
#include <math_constants.h>
#include <mma.h>

using namespace nvcuda;

// Problem constants
#define B_    128
#define T_    1024
#define D_    512
#define V_    128
#define L_    128
#define S_    257           // 2L+1
#define BLANK_ 127          // V-1
#define EPS_  1e-7f
#define NEG_  (-1e30f)
#define LN2_  0.6931471805599453f
#define TMID_ 512           // meet point: forward owns t<=511, backward t>=512

// GEMM tiling
#define BM 128
#define BN 128
#define BK 16
#define NCHUNK (D_ / BK)    // 32
#define NSTAGE 4
#define AFPAD 4
#define BFPAD 4
#define ABPAD 8
#define BBPAD 8
#define CPAD 4

// Dynamic smem layout (bytes)
#define AFP_STRIDE ((BK + AFPAD) * 4)                  // 80 B per A row
#define AFP_STAGE  (BM * AFP_STRIDE)                   // 10240
#define BFP_STRIDE ((BN + BFPAD) * 4)                  // 528 B per B row
#define BFP_STAGE  (BK * BFP_STRIDE)                   // 8448
#define OFF_AFP    0
#define OFF_BFP    (NSTAGE * AFP_STAGE)                // 40960
#define OFF_AB     (OFF_BFP + NSTAGE * BFP_STAGE)      // 74752
#define AB_BYTES   (BM * (BK + ABPAD) * 2)             // 6144
#define OFF_BB     (OFF_AB + AB_BYTES)                 // 80896
#define BB_BYTES   (BK * (BN + BBPAD) * 2)             // 4352
#define SMEM_DYN   (OFF_BB + BB_BYTES)                 // 85248

// Scratch
static __device__ float g_lp[B_ * T_ * V_];    // log2(softmax+eps), 64 MB
static __device__ float g_amid[B_ * S_];       // forward alpha at t=511
static __device__ float g_bmid[B_ * S_];       // backward gamma at t=511
static __device__ float g_loss[B_];

__device__ __forceinline__ float fexp2(float x) {
    float y; asm("ex2.approx.ftz.f32 %0, %1;" : "=f"(y) : "f"(x)); return y;
}

__device__ __forceinline__ void st4bf16(__nv_bfloat16* dst, float4 v) {
    __nv_bfloat162 p0; p0.x = __float2bfloat16(v.x); p0.y = __float2bfloat16(v.y);
    __nv_bfloat162 p1; p1.x = __float2bfloat16(v.z); p1.y = __float2bfloat16(v.w);
    *(__nv_bfloat162*)(dst)     = p0;
    *(__nv_bfloat162*)(dst + 2) = p1;
}

__device__ __forceinline__ void cp16cg(void* dst_smem, const void* src) {
    unsigned d = (unsigned)__cvta_generic_to_shared(dst_smem);
    asm volatile("cp.async.cg.shared.global [%0], [%1], 16;\n" :: "r"(d), "l"(src));
}

// ---------------------------------------------------------------------------
// Kernel 1: bf16 WMMA GEMM (logits = X @ W + b) + softmax -> g_lp = log2(p+eps)
// M = 131072, N = 128, K = 512, fp32 accumulate.
// 4-stage cp.async.cg pipeline on RAW fp32 (wait_group 2 -> 3 stages / 49 KB
// per CTA continuously in flight; kills the load-burst convoy). Per chunk:
// wait, bar, fp32->bf16 convert into shared bufs, bar, issue c+3, bf16 WMMA.
// Block 128x128, BK=16, 8 warps (4M x 2N), warp tile 32x64.
// ---------------------------------------------------------------------------
__global__ __launch_bounds__(256) void gemm_softmax_kernel(
    const float* __restrict__ X, const float* __restrict__ W,
    const float* __restrict__ bias)
{
    extern __shared__ __align__(16) char smem[];
    // stage pointers
    auto Afp = [&](int st, int r) -> float* {
        return (float*)(smem + OFF_AFP + st * AFP_STAGE + r * AFP_STRIDE);
    };
    auto Bfp = [&](int st, int r) -> float* {
        return (float*)(smem + OFF_BFP + st * BFP_STAGE + r * BFP_STRIDE);
    };
    __nv_bfloat16* Ab = (__nv_bfloat16*)(smem + OFF_AB);   // [BM][BK+ABPAD]
    __nv_bfloat16* Bb = (__nv_bfloat16*)(smem + OFF_BB);   // [BK][BN+BBPAD]
    float* Cs = (float*)smem;                               // epilogue alias [32][BN+CPAD]

    const int tid = threadIdx.x;
    const int wid = tid >> 5;
    const int warp_m = wid & 3;       // 0..3
    const int warp_n = wid >> 2;      // 0..1
    const int rowBase = blockIdx.x * BM;

    wmma::fragment<wmma::accumulator, 16, 16, 16, float> cfrag[2][4];
#pragma unroll
    for (int i = 0; i < 2; ++i)
#pragma unroll
        for (int j = 0; j < 4; ++j) wmma::fill_fragment(cfrag[i][j], 0.f);

    // mapping: A chunk 128x16 fp32 (2 thr/row, 8 floats each);
    //          B chunk  16x128 fp32 (16 thr/row, 8 floats each)
    const int ar = tid >> 1;
    const int ac = (tid & 1) * 8;
    const int br = tid >> 4;
    const int bc = (tid & 15) * 8;
    const float* Ap = X + (size_t)(rowBase + ar) * D_ + ac;
    const float* Bp = W + (size_t)br * V_ + bc;

#define ISSUE_CHUNK(C)                                                        \
    {   const int st_ = (C) % NSTAGE; const int k0_ = (C) * BK;               \
        cp16cg(Afp(st_, ar) + ac,     Ap + k0_);                              \
        cp16cg(Afp(st_, ar) + ac + 4, Ap + k0_ + 4);                          \
        cp16cg(Bfp(st_, br) + bc,     Bp + (size_t)k0_ * V_);                 \
        cp16cg(Bfp(st_, br) + bc + 4, Bp + (size_t)k0_ * V_ + 4); }

    // Prologue: issue chunks 0..2 (3 groups)
    ISSUE_CHUNK(0); asm volatile("cp.async.commit_group;\n");
    ISSUE_CHUNK(1); asm volatile("cp.async.commit_group;\n");
    ISSUE_CHUNK(2); asm volatile("cp.async.commit_group;\n");

    for (int c = 0; c < NCHUNK; ++c) {
        const int st = c % NSTAGE;
        asm volatile("cp.async.wait_group 2;\n");   // chunk c's stage arrived
        __syncthreads();                            // visible to all; MMA(c-1) done

        // Convert fp32 stage -> shared bf16 tiles
        {
            float4 a0 = *(const float4*)(Afp(st, ar) + ac);
            float4 a1 = *(const float4*)(Afp(st, ar) + ac + 4);
            float4 b0 = *(const float4*)(Bfp(st, br) + bc);
            float4 b1 = *(const float4*)(Bfp(st, br) + bc + 4);
            st4bf16(Ab + ar * (BK + ABPAD) + ac,     a0);
            st4bf16(Ab + ar * (BK + ABPAD) + ac + 4, a1);
            st4bf16(Bb + br * (BN + BBPAD) + bc,     b0);
            st4bf16(Bb + br * (BN + BBPAD) + bc + 4, b1);
        }
        __syncthreads();

        // Refill stage (c+3)%NSTAGE (its fp32 was consumed at chunk c-1)
        if (c + 3 < NCHUNK) ISSUE_CHUNK(c + 3);
        asm volatile("cp.async.commit_group;\n");   // uniform group accounting

        // bf16 WMMA on the converted tiles (k = 16, single step)
        wmma::fragment<wmma::matrix_a, 16, 16, 16, __nv_bfloat16, wmma::row_major> af[2];
        wmma::fragment<wmma::matrix_b, 16, 16, 16, __nv_bfloat16, wmma::row_major> bf[4];
#pragma unroll
        for (int i = 0; i < 2; ++i)
            wmma::load_matrix_sync(af[i], Ab + (warp_m * 32 + i * 16) * (BK + ABPAD), BK + ABPAD);
#pragma unroll
        for (int j = 0; j < 4; ++j)
            wmma::load_matrix_sync(bf[j], Bb + (warp_n * 64 + j * 16), BN + BBPAD);
#pragma unroll
        for (int i = 0; i < 2; ++i)
#pragma unroll
            for (int j = 0; j < 4; ++j)
                wmma::mma_sync(cfrag[i][j], af[i], bf[j], cfrag[i][j]);
    }
#undef ISSUE_CHUNK
    __syncthreads();   // all MMA/convert reads done before Cs aliases the stages

    // Epilogue: 4 passes of 32 rows through Cs. Softmax, write log2(p+eps).
    const int tx = tid & 15;
    const int ty = tid >> 4;
    float bb[8];
#pragma unroll
    for (int j = 0; j < 8; ++j) bb[j] = bias[tx * 8 + j];

    for (int wm = 0; wm < 4; ++wm) {
        if (warp_m == wm) {
#pragma unroll
            for (int i = 0; i < 2; ++i)
#pragma unroll
                for (int j = 0; j < 4; ++j)
                    wmma::store_matrix_sync(Cs + (i * 16) * (BN + CPAD) + warp_n * 64 + j * 16,
                                            cfrag[i][j], BN + CPAD, wmma::mem_row_major);
        }
        __syncthreads();
#pragma unroll
        for (int r = 0; r < 2; ++r) {
            const int row = ty * 2 + r;
            float l[8];
            float rmax = -CUDART_INF_F;
#pragma unroll
            for (int j = 0; j < 8; ++j) {
                l[j] = Cs[row * (BN + CPAD) + tx * 8 + j] + bb[j];
                rmax = fmaxf(rmax, l[j]);
            }
#pragma unroll
            for (int m = 1; m <= 8; m <<= 1)
                rmax = fmaxf(rmax, __shfl_xor_sync(0xFFFFFFFFu, rmax, m));
            float s = 0.f;
#pragma unroll
            for (int j = 0; j < 8; ++j) { l[j] = __expf(l[j] - rmax); s += l[j]; }
#pragma unroll
            for (int m = 1; m <= 8; m <<= 1)
                s += __shfl_xor_sync(0xFFFFFFFFu, s, m);
            float invs = 1.f / s;
            float* orow = g_lp + (size_t)(rowBase + wm * 32 + row) * V_ + tx * 8;
            float4 o0, o1;
            o0.x = __log2f(l[0] * invs + EPS_); o0.y = __log2f(l[1] * invs + EPS_);
            o0.z = __log2f(l[2] * invs + EPS_); o0.w = __log2f(l[3] * invs + EPS_);
            o1.x = __log2f(l[4] * invs + EPS_); o1.y = __log2f(l[5] * invs + EPS_);
            o1.z = __log2f(l[6] * invs + EPS_); o1.w = __log2f(l[7] * invs + EPS_);
            *(float4*)orow = o0;
            *(float4*)(orow + 4) = o1;
        }
        __syncthreads();
    }
}

// ---------------------------------------------------------------------------
// Kernel 2: CTC meet-in-the-middle (R15 verbatim — measured ~82 us).
// ---------------------------------------------------------------------------
__global__ __launch_bounds__(288) void ctc_fb_kernel(
    const int* __restrict__ targets, const int* __restrict__ tlen)
{
    __shared__ float buf[2][S_];
    __shared__ int   exts[S_];

    const int bid = blockIdx.x;
    const bool fw = (bid < B_);
    const int b   = fw ? bid : bid - B_;
    const int tid = threadIdx.x;
    const bool act = (tid < S_);
    const float* LP = g_lp + (size_t)b * T_ * V_;

    if (act) exts[tid] = (tid & 1) ? targets[b * L_ + (tid >> 1)] : BLANK_;
    __syncthreads();

    int myext = BLANK_;
    if (act) myext = exts[tid];

    if (fw) {
        const bool allow2 = act && (tid & 1) && (tid >= 2) && (myext != exts[tid - 2]);
        if (act) buf[0][tid] = (tid < 2) ? LP[myext] : NEG_;
        float e[8];
#pragma unroll
        for (int j = 0; j < 8; ++j) e[j] = LP[(size_t)(1 + j) * V_ + myext];
        __syncthreads();

        for (int t0 = 1; t0 <= TMID_ - 15; t0 += 8) {
#pragma unroll
            for (int j = 0; j < 8; ++j) {
                const int cur  = (1 + j) & 1;
                const int prev = cur ^ 1;
                if (act) {
                    float a  = buf[prev][tid];
                    float a1 = (tid >= 1) ? buf[prev][tid - 1] : NEG_;
                    float a2 = allow2 ? buf[prev][tid - 2] : NEG_;
                    float m  = fmaxf(fmaxf(a, a1), a2);
                    float s  = fexp2(a - m) + fexp2(a1 - m) + fexp2(a2 - m);
                    buf[cur][tid] = m + __log2f(s) + e[j];
                }
                const int tn = t0 + 8 + j;
                if (tn < TMID_) e[j] = LP[(size_t)tn * V_ + myext];
                __syncthreads();
            }
        }
#pragma unroll
        for (int j = 0; j < 7; ++j) {             // t = 505..511
            const int cur  = (505 + j) & 1;
            const int prev = cur ^ 1;
            if (act) {
                float a  = buf[prev][tid];
                float a1 = (tid >= 1) ? buf[prev][tid - 1] : NEG_;
                float a2 = allow2 ? buf[prev][tid - 2] : NEG_;
                float m  = fmaxf(fmaxf(a, a1), a2);
                float s  = fexp2(a - m) + fexp2(a1 - m) + fexp2(a2 - m);
                buf[cur][tid] = m + __log2f(s) + e[j];
            }
            __syncthreads();
        }
        if (act) g_amid[b * S_ + tid] = buf[1][tid];
    } else {
        bool allow2b = false;
        if (act && (tid & 1) && (tid + 2 < S_)) allow2b = (exts[tid + 2] != myext);
        const int last = 2 * tlen[b];
        if (act) buf[1][tid] = (tid == last || tid == last - 1)
                                   ? LP[(size_t)1023 * V_ + myext] : NEG_;
        float e[8];
#pragma unroll
        for (int j = 0; j < 8; ++j) e[j] = LP[(size_t)(1022 - j) * V_ + myext];
        __syncthreads();

        for (int t0 = 1022; t0 >= 519 + 7; t0 -= 8) {
#pragma unroll
            for (int j = 0; j < 8; ++j) {
                const int t    = t0 - j;
                const int cur  = t & 1;
                const int prev = cur ^ 1;
                if (act) {
                    float v0 = buf[prev][tid];
                    float v1 = (tid + 1 < S_) ? buf[prev][tid + 1] : NEG_;
                    float v2 = allow2b ? buf[prev][tid + 2] : NEG_;
                    float m  = fmaxf(fmaxf(v0, v1), v2);
                    float s  = fexp2(v0 - m) + fexp2(v1 - m) + fexp2(v2 - m);
                    buf[cur][tid] = m + __log2f(s) + e[j];
                }
                const int tn = t - 8;
                if (tn >= TMID_) e[j] = LP[(size_t)tn * V_ + myext];
                __syncthreads();
            }
        }
#pragma unroll
        for (int j = 0; j < 7; ++j) {             // t = 518..512
            const int t    = 518 - j;
            const int cur  = t & 1;
            const int prev = cur ^ 1;
            if (act) {
                float v0 = buf[prev][tid];
                float v1 = (tid + 1 < S_) ? buf[prev][tid + 1] : NEG_;
                float v2 = allow2b ? buf[prev][tid + 2] : NEG_;
                float m  = fmaxf(fmaxf(v0, v1), v2);
                float s  = fexp2(v0 - m) + fexp2(v1 - m) + fexp2(v2 - m);
                buf[cur][tid] = m + __log2f(s) + e[j];
            }
            __syncthreads();
        }
        if (act) {
            float v0 = buf[0][tid];
            float v1 = (tid + 1 < S_) ? buf[0][tid + 1] : NEG_;
            float v2 = allow2b ? buf[0][tid + 2] : NEG_;
            float m  = fmaxf(fmaxf(v0, v1), v2);
            float s  = fexp2(v0 - m) + fexp2(v1 - m) + fexp2(v2 - m);
            g_bmid[b * S_ + tid] = m + __log2f(s);
        }
    }
}

// ---------------------------------------------------------------------------
// Kernel 3: combine — per-example logsumexp over 257 states.
// ---------------------------------------------------------------------------
__global__ __launch_bounds__(288) void combine_kernel(void)
{
    __shared__ float wred[9];
    const int b    = blockIdx.x;
    const int tid  = threadIdx.x;
    const int lane = tid & 31;
    const int warp = tid >> 5;
    const bool act = (tid < S_);

    float v = act ? (g_amid[b * S_ + tid] + g_bmid[b * S_ + tid]) : NEG_;

    float m = v;
#pragma unroll
    for (int o = 16; o > 0; o >>= 1)
        m = fmaxf(m, __shfl_xor_sync(0xFFFFFFFFu, m, o));
    if (lane == 0) wred[warp] = m;
    __syncthreads();
    float M = wred[0];
#pragma unroll
    for (int w = 1; w < 9; ++w) M = fmaxf(M, wred[w]);
    __syncthreads();

    float s = act ? fexp2(v - M) : 0.f;
#pragma unroll
    for (int o = 16; o > 0; o >>= 1)
        s += __shfl_xor_sync(0xFFFFFFFFu, s, o);
    if (lane == 0) wred[warp] = s;
    __syncthreads();
    if (tid == 0) {
        float tot = wred[0];
#pragma unroll
        for (int w = 1; w < 9; ++w) tot += wred[w];
        g_loss[b] = -LN2_ * (M + __log2f(tot));
    }
}

// ---------------------------------------------------------------------------
// Kernel 4: deterministic fixed-order sum of the 128 losses.
// ---------------------------------------------------------------------------
__global__ __launch_bounds__(128) void sum_kernel(float* __restrict__ out)
{
    __shared__ float s[128];
    const int t = threadIdx.x;
    s[t] = g_loss[t];
    __syncthreads();
    for (int o = 64; o > 0; o >>= 1) {
        if (t < o) s[t] += s[t + o];
        __syncthreads();
    }
    if (t == 0) out[0] = s[0];
}

extern "C" void kernel_launch(void* const* d_in, const int* in_sizes, int n_in,
                              void* d_out, int out_size)
{
    (void)in_sizes; (void)n_in; (void)out_size;
    const float* x       = (const float*)d_in[0];
    const float* W       = (const float*)d_in[1];
    const float* bias    = (const float*)d_in[2];
    const int*   targets = (const int*)d_in[3];
    const int*   tlength = (const int*)d_in[4];

    cudaFuncSetAttribute(gemm_softmax_kernel,
                         cudaFuncAttributeMaxDynamicSharedMemorySize, SMEM_DYN);

    gemm_softmax_kernel<<<(B_ * T_) / BM, 256, SMEM_DYN>>>(x, W, bias);
    ctc_fb_kernel<<<2 * B_, 288>>>(targets, tlength);
    combine_kernel<<<B_, 288>>>();
    sum_kernel<<<1, 128>>>((float*)d_out);
}